// round 16
// baseline (speedup 1.0000x reference)
#include <cuda_runtime.h>
#include <cooperative_groups.h>
#include <cstdint>

namespace cg = cooperative_groups;

typedef unsigned long long u64;

#define NB    4
#define NPTS  16384
#define NC    64
#define NSMP  1024      // S (npoint)
#define NNEI  32        // nsample
#define D0    67        // 3 + C
#define D1    64
#define D2    64
#define D3    128

#define FCTAS 4                 // cluster size (CTAs per batch)
#define FTHR  512               // threads per FPS CTA
#define PPC   (NPTS / FCTAS)    // 4096 points per CTA
#define PPT   (PPC / FTHR)      // 8 points per thread
#define NWARP (FTHR / 32)       // 16 warps
#define NRECS (2 * FCTAS)       // 8 records per rendezvous (top-2 per CTA)

#define NTASK (NB * NSMP)       // 4096 centroid tasks
#define NPAIR (NTASK / 2)       // 2048 task pairs
#define MLPC  148               // persistent dual-task MLP CTAs (1 per SM)

// scratch: ball query neighbor indices
__device__ int g_ball_idx[NB * NSMP * NNEI];

__device__ __forceinline__ unsigned smem_u32(const void* p) {
    return (unsigned)__cvta_generic_to_shared(p);
}
__device__ __forceinline__ unsigned mapa_u32(unsigned laddr, unsigned rank) {
    unsigned r;
    asm("mapa.shared::cluster.u32 %0, %1, %2;" : "=r"(r) : "r"(laddr), "r"(rank));
    return r;
}
__device__ __forceinline__ void st_cluster_f4(unsigned raddr, float x, float y, float z, float w) {
    asm volatile("st.shared::cluster.v4.f32 [%0], {%1,%2,%3,%4};"
                 :: "r"(raddr), "f"(x), "f"(y), "f"(z), "f"(w) : "memory");
}
__device__ __forceinline__ void st_cluster_u64(unsigned raddr, u64 v) {
    asm volatile("st.shared::cluster.u64 [%0], %1;" :: "r"(raddr), "l"(v) : "memory");
}
__device__ __forceinline__ unsigned redux_max_u32(unsigned v) {
    unsigned r;
    asm("redux.sync.max.u32 %0, %1, 0xffffffff;" : "=r"(r) : "r"(v));
    return r;
}
__device__ __forceinline__ void cluster_arrive() {
    asm volatile("barrier.cluster.arrive.aligned;" ::: "memory");
}
__device__ __forceinline__ void cluster_wait() {
    asm volatile("barrier.cluster.wait.aligned;" ::: "memory");
}
// shared distance expression: update pass and candidate eval MUST match bitwise
__device__ __forceinline__ float d2f(float dx, float dy, float dz) {
    return dx * dx + dy * dy + dz * dz;
}
__device__ __forceinline__ u64 pk(unsigned hi, unsigned lo) {
    return ((u64)hi << 32) | lo;
}

// ---------------------------------------------------------------------------
// FPS with exact double-selection: each rendezvous exchanges top-2 per CTA;
// if the best post-c1 candidate key provably dominates all hidden points
// (>= max t2key), two centroids are emitted per rendezvous.
// ---------------------------------------------------------------------------
__global__ __launch_bounds__(FTHR, 1) __cluster_dims__(FCTAS, 1, 1)
void fps_cluster_kernel(const float* __restrict__ xyz, float* __restrict__ out_xyz) {
    extern __shared__ float dsm[];
    float* sx = dsm;
    float* sy = dsm + PPC;
    float* sz = dsm + 2 * PPC;
    __shared__ alignas(16) u64 s_k[2][NRECS];     // record keys
    __shared__ float4 s_c[2][NRECS];              // record coords
    __shared__ u64 s_wk[2 * NWARP];               // warp top-2 keys (32)

    cg::cluster_group cluster = cg::this_cluster();
    const int crank = cluster.block_rank();
    const int b     = blockIdx.x / FCTAS;
    const int tid   = threadIdx.x;
    const int lane  = tid & 31;
    const int wid   = tid >> 5;

    const float* base = xyz + (size_t)b * NPTS * 3;
    const int g0 = crank * PPC;

    for (int k = tid; k < PPC * 3; k += FTHR) {
        float v = base[(size_t)g0 * 3 + k];
        int p = k / 3, c = k - 3 * p;
        if (c == 0)      sx[p] = v;
        else if (c == 1) sy[p] = v;
        else             sz[p] = v;
    }
    cluster.sync();

    float px[PPT], py[PPT], pz[PPT], dist[PPT];
#pragma unroll
    for (int j = 0; j < PPT; j++) {
        int i = tid + j * FTHR;
        px[j] = sx[i]; py[j] = sy[i]; pz[j] = sz[i];
        dist[j] = 3.4e38f;
    }

    // remote push addrs (wid 0, lane r -> peer rank r), 2 records x 2 parities
    unsigned ak[2][2], ac[2][2];
    if (wid == 0 && lane < FCTAS) {
#pragma unroll
        for (int q = 0; q < 2; q++) {
            ak[q][0] = mapa_u32(smem_u32(&s_k[q][crank * 2]),     lane);
            ak[q][1] = mapa_u32(smem_u32(&s_k[q][crank * 2 + 1]), lane);
            ac[q][0] = mapa_u32(smem_u32(&s_c[q][crank * 2]),     lane);
            ac[q][1] = mapa_u32(smem_u32(&s_c[q][crank * 2 + 1]), lane);
        }
    }

    float* oxy = out_xyz + (size_t)b * NSMP * 3;

    // centroid 0 = point 0
    float ax = base[0], ay = base[1], az = base[2];
    float bx2 = 0.f, by2 = 0.f, bz2 = 0.f;
    bool haveB = false;
    if (crank == 0 && tid == 0) {
        oxy[0] = ax; oxy[1] = ay; oxy[2] = az;
    }

    int s = 1;   // next output index
    int r = 0;   // rendezvous counter (parity)

    while (s < NSMP) {
        // ---- update with pending centroid(s) + thread top-2 ----
        u64 k1 = 0ull, k2 = 0ull;
#pragma unroll
        for (int j = 0; j < PPT; j++) {
            float da = d2f(px[j] - ax, py[j] - ay, pz[j] - az);
            float nd = fminf(dist[j], da);
            if (haveB) {
                float db = d2f(px[j] - bx2, py[j] - by2, pz[j] - bz2);
                nd = fminf(nd, db);
            }
            dist[j] = nd;
            u64 key = pk(__float_as_uint(nd),
                         0xffffffffu - (unsigned)(g0 + tid + j * FTHR));
            if (key > k1)      { k2 = k1; k1 = key; }
            else if (key > k2) { k2 = key; }
        }

        // ---- warp top-2 via redux ----
        unsigned h1 = (unsigned)(k1 >> 32), l1 = (unsigned)k1;
        unsigned h2 = (unsigned)(k2 >> 32), l2 = (unsigned)k2;
        unsigned t1h = redux_max_u32(h1);
        unsigned t1l = redux_max_u32((h1 == t1h) ? l1 : 0u);
        bool isw = (h1 == t1h) && (l1 == t1l);
        unsigned ch = isw ? h2 : h1, cl = isw ? l2 : l1;
        unsigned t2h = redux_max_u32(ch);
        unsigned t2l = redux_max_u32((ch == t2h) ? cl : 0u);
        if (lane == 0) {
            s_wk[wid * 2]     = pk(t1h, t1l);
            s_wk[wid * 2 + 1] = pk(t2h, t2l);
        }
        __syncthreads();

        const int par = r & 1;
        if (wid == 0) {
            // CTA top-2 over 32 warp entries (lane-parallel)
            u64 e = s_wk[lane];
            unsigned eh = (unsigned)(e >> 32), el = (unsigned)e;
            unsigned T1h = redux_max_u32(eh);
            unsigned T1l = redux_max_u32((eh == T1h) ? el : 0u);
            bool ex = (eh == T1h) && (el == T1l);
            unsigned c2h_ = ex ? 0u : eh;
            unsigned T2h = redux_max_u32(c2h_);
            unsigned T2l = redux_max_u32((!ex && eh == T2h) ? el : 0u);
            if (lane < FCTAS) {
                int li1 = (int)(0xffffffffu - T1l) - g0;
                int li2 = (int)(0xffffffffu - T2l) - g0;
                st_cluster_u64(ak[par][0], pk(T1h, T1l));
                st_cluster_f4(ac[par][0], sx[li1], sy[li1], sz[li1], 0.0f);
                st_cluster_u64(ak[par][1], pk(T2h, T2l));
                st_cluster_f4(ac[par][1], sx[li2], sy[li2], sz[li2], 0.0f);
            }
        }
        cluster_arrive();
        cluster_wait();
        r++;

        // ---- all threads: read records, pick c1, certify c2 ----
        u64 kk[NRECS];
        u64 c1k = 0ull; int c1s = 0;
#pragma unroll
        for (int i = 0; i < NRECS; i++) {
            kk[i] = s_k[par][i];
            if (kk[i] > c1k) { c1k = kk[i]; c1s = i; }
        }
        // hidden bound: max of the four t2 keys (odd slots)
        u64 BK = kk[1];
        if (kk[3] > BK) BK = kk[3];
        if (kk[5] > BK) BK = kk[5];
        if (kk[7] > BK) BK = kk[7];
        float4 c1c = s_c[par][c1s];

        u64 bv = 0ull; int bslot = 0;
#pragma unroll
        for (int i = 0; i < NRECS; i++) {
            if (i == c1s) continue;
            float oldv = __uint_as_float((unsigned)(kk[i] >> 32));
            float4 q = s_c[par][i];
            float v = fminf(oldv, d2f(q.x - c1c.x, q.y - c1c.y, q.z - c1c.z));
            u64 vk = pk(__float_as_uint(v), (unsigned)kk[i]);
            if (vk > bv) { bv = vk; bslot = i; }
        }
        bool pairOK = (s + 2 <= NSMP) && (bv >= BK);

        if (crank == 0 && tid == 0) {
            oxy[s * 3 + 0] = c1c.x; oxy[s * 3 + 1] = c1c.y; oxy[s * 3 + 2] = c1c.z;
        }
        ax = c1c.x; ay = c1c.y; az = c1c.z;
        if (pairOK) {
            float4 c2c = s_c[par][bslot];
            if (crank == 0 && tid == 0) {
                oxy[(s + 1) * 3 + 0] = c2c.x;
                oxy[(s + 1) * 3 + 1] = c2c.y;
                oxy[(s + 1) * 3 + 2] = c2c.z;
            }
            bx2 = c2c.x; by2 = c2c.y; bz2 = c2c.z;
            haveB = true;
            s += 2;
        } else {
            haveB = false;
            s += 1;
        }
    }
}

// ---------------------------------------------------------------------------
// Ball query: one warp per centroid, 128-point pipelined chunks.
// ---------------------------------------------------------------------------
__global__ void ball_kernel(const float* __restrict__ xyz,
                            const float* __restrict__ new_xyz) {
    const int gw   = (blockIdx.x * blockDim.x + threadIdx.x) >> 5;
    const int lane = threadIdx.x & 31;
    if (gw >= NB * NSMP) return;
    const int b = gw >> 10;
    const float* base = xyz + (size_t)b * NPTS * 3;
    const float cx = new_xyz[gw * 3 + 0];
    const float cy = new_xyz[gw * 3 + 1];
    const float cz = new_xyz[gw * 3 + 2];
    const float r2 = 0.2f * 0.2f;
    int* out = g_ball_idx + gw * NNEI;

    int cnt = 0, first = 0;
    for (int j0 = 0; j0 < NPTS && cnt < NNEI; j0 += 128) {
        float d2v[4];
#pragma unroll
        for (int c = 0; c < 4; c++) {
            const int j = j0 + c * 32 + lane;
            float dx = base[3 * j]     - cx;
            float dy = base[3 * j + 1] - cy;
            float dz = base[3 * j + 2] - cz;
            d2v[c] = dx * dx + dy * dy + dz * dz;
        }
#pragma unroll
        for (int c = 0; c < 4; c++) {
            bool hit = (d2v[c] <= r2);
            unsigned m = __ballot_sync(0xffffffffu, hit);
            if (m) {
                if (cnt == 0) first = j0 + c * 32 + (__ffs(m) - 1);
                int pos = cnt + __popc(m & ((1u << lane) - 1u));
                if (hit && pos < NNEI) out[pos] = j0 + c * 32 + lane;
                cnt += __popc(m);
            }
        }
    }
    if (cnt < NNEI) {
        for (int p = cnt + lane; p < NNEI; p += 32) out[p] = first;
    }
}

// ---------------------------------------------------------------------------
// Dual-task persistent MLP (R15, proven).
// ---------------------------------------------------------------------------
__global__ __launch_bounds__(256, 1)
void group_mlp_kernel(const float* __restrict__ xyz,
                      const float* __restrict__ feat,
                      const float* __restrict__ W0, const float* __restrict__ b0,
                      const float* __restrict__ W1, const float* __restrict__ b1,
                      const float* __restrict__ W2, const float* __restrict__ b2,
                      const float* __restrict__ new_xyz,
                      float* __restrict__ out_feat) {
    extern __shared__ float sm[];
    float* W0s = sm;
    float* W1s = W0s + D0 * D1;
    float* W2s = W1s + D1 * D2;
    float* b0s = W2s + D2 * D3;
    float* b1s = b0s + D1;
    float* b2s = b1s + D2;
    float* hA0 = b2s + D3;
    float* hA1 = hA0 + NNEI * D0;
    float* hB0 = hA1 + NNEI * D0;
    float* hB1 = hB0 + NNEI * D3;
    float* hC0 = hB1 + NNEI * D3;
    float* hC1 = hC0 + NNEI * D2;

    const int tid = threadIdx.x;
    const int chq = tid & 15;
    const int ns0 = (tid >> 4) * 2;

    for (int i = tid; i < D0 * D1; i += 256) W0s[i] = W0[i];
    for (int i = tid; i < D1 * D2; i += 256) W1s[i] = W1[i];
    for (int i = tid; i < D2 * D3; i += 256) W2s[i] = W2[i];
    if (tid < D1) b0s[tid] = b0[tid];
    if (tid < D2) b1s[tid] = b1[tid];
    if (tid < D3) b2s[tid] = b2[tid];
    __syncthreads();

    for (int p = blockIdx.x; p < NPAIR; p += MLPC) {
        const int cid0 = 2 * p;
        const int cid1 = 2 * p + 1;
        const int ba = cid0 >> 10;
        const float* xb = xyz  + (size_t)ba * NPTS * 3;
        const float* fb = feat + (size_t)ba * NPTS * NC;
        const int* ni0 = g_ball_idx + cid0 * NNEI;
        const int* ni1 = g_ball_idx + cid1 * NNEI;

        for (int e = tid; e < NNEI * 3; e += 256) {
            int ns = e / 3, k = e - 3 * ns;
            hA0[ns * D0 + k] = xb[(size_t)__ldg(ni0 + ns) * 3 + k]
                               - new_xyz[cid0 * 3 + k];
            hA1[ns * D0 + k] = xb[(size_t)__ldg(ni1 + ns) * 3 + k]
                               - new_xyz[cid1 * 3 + k];
        }
        for (int e = tid; e < NNEI * NC; e += 256) {
            int ns = e >> 6, c = e & 63;
            hA0[ns * D0 + 3 + c] = fb[(size_t)__ldg(ni0 + ns) * NC + c];
            hA1[ns * D0 + 3 + c] = fb[(size_t)__ldg(ni1 + ns) * NC + c];
        }
        __syncthreads();

        // ---- layer 1 ----
        {
            float4 bs = *(float4*)&b0s[chq * 4];
            float p00 = bs.x, p01 = bs.y, p02 = bs.z, p03 = bs.w;
            float p10 = bs.x, p11 = bs.y, p12 = bs.z, p13 = bs.w;
            float q00 = bs.x, q01 = bs.y, q02 = bs.z, q03 = bs.w;
            float q10 = bs.x, q11 = bs.y, q12 = bs.z, q13 = bs.w;
            const float* p0 = hA0 + ns0 * D0;
            const float* p1 = hA0 + (ns0 + 1) * D0;
            const float* q0 = hA1 + ns0 * D0;
            const float* q1 = hA1 + (ns0 + 1) * D0;
#pragma unroll 4
            for (int d = 0; d < D0; d++) {
                float4 w = *(float4*)&W0s[d * D1 + chq * 4];
                float a = p0[d], b_ = p1[d], c = q0[d], e = q1[d];
                p00 = fmaf(a, w.x, p00); p01 = fmaf(a, w.y, p01);
                p02 = fmaf(a, w.z, p02); p03 = fmaf(a, w.w, p03);
                p10 = fmaf(b_, w.x, p10); p11 = fmaf(b_, w.y, p11);
                p12 = fmaf(b_, w.z, p12); p13 = fmaf(b_, w.w, p13);
                q00 = fmaf(c, w.x, q00); q01 = fmaf(c, w.y, q01);
                q02 = fmaf(c, w.z, q02); q03 = fmaf(c, w.w, q03);
                q10 = fmaf(e, w.x, q10); q11 = fmaf(e, w.y, q11);
                q12 = fmaf(e, w.z, q12); q13 = fmaf(e, w.w, q13);
            }
            *(float4*)&hB0[ns0 * D1 + chq * 4] =
                make_float4(fmaxf(p00, 0.f), fmaxf(p01, 0.f), fmaxf(p02, 0.f), fmaxf(p03, 0.f));
            *(float4*)&hB0[(ns0 + 1) * D1 + chq * 4] =
                make_float4(fmaxf(p10, 0.f), fmaxf(p11, 0.f), fmaxf(p12, 0.f), fmaxf(p13, 0.f));
            *(float4*)&hB1[ns0 * D1 + chq * 4] =
                make_float4(fmaxf(q00, 0.f), fmaxf(q01, 0.f), fmaxf(q02, 0.f), fmaxf(q03, 0.f));
            *(float4*)&hB1[(ns0 + 1) * D1 + chq * 4] =
                make_float4(fmaxf(q10, 0.f), fmaxf(q11, 0.f), fmaxf(q12, 0.f), fmaxf(q13, 0.f));
        }
        __syncthreads();

        // ---- layer 2 ----
        {
            float4 bs = *(float4*)&b1s[chq * 4];
            float p00 = bs.x, p01 = bs.y, p02 = bs.z, p03 = bs.w;
            float p10 = bs.x, p11 = bs.y, p12 = bs.z, p13 = bs.w;
            float q00 = bs.x, q01 = bs.y, q02 = bs.z, q03 = bs.w;
            float q10 = bs.x, q11 = bs.y, q12 = bs.z, q13 = bs.w;
            const float* p0 = hB0 + ns0 * D1;
            const float* p1 = hB0 + (ns0 + 1) * D1;
            const float* q0 = hB1 + ns0 * D1;
            const float* q1 = hB1 + (ns0 + 1) * D1;
#pragma unroll 4
            for (int d = 0; d < D1; d++) {
                float4 w = *(float4*)&W1s[d * D2 + chq * 4];
                float a = p0[d], b_ = p1[d], c = q0[d], e = q1[d];
                p00 = fmaf(a, w.x, p00); p01 = fmaf(a, w.y, p01);
                p02 = fmaf(a, w.z, p02); p03 = fmaf(a, w.w, p03);
                p10 = fmaf(b_, w.x, p10); p11 = fmaf(b_, w.y, p11);
                p12 = fmaf(b_, w.z, p12); p13 = fmaf(b_, w.w, p13);
                q00 = fmaf(c, w.x, q00); q01 = fmaf(c, w.y, q01);
                q02 = fmaf(c, w.z, q02); q03 = fmaf(c, w.w, q03);
                q10 = fmaf(e, w.x, q10); q11 = fmaf(e, w.y, q11);
                q12 = fmaf(e, w.z, q12); q13 = fmaf(e, w.w, q13);
            }
            *(float4*)&hC0[ns0 * D2 + chq * 4] =
                make_float4(fmaxf(p00, 0.f), fmaxf(p01, 0.f), fmaxf(p02, 0.f), fmaxf(p03, 0.f));
            *(float4*)&hC0[(ns0 + 1) * D2 + chq * 4] =
                make_float4(fmaxf(p10, 0.f), fmaxf(p11, 0.f), fmaxf(p12, 0.f), fmaxf(p13, 0.f));
            *(float4*)&hC1[ns0 * D2 + chq * 4] =
                make_float4(fmaxf(q00, 0.f), fmaxf(q01, 0.f), fmaxf(q02, 0.f), fmaxf(q03, 0.f));
            *(float4*)&hC1[(ns0 + 1) * D2 + chq * 4] =
                make_float4(fmaxf(q10, 0.f), fmaxf(q11, 0.f), fmaxf(q12, 0.f), fmaxf(q13, 0.f));
        }
        __syncthreads();

        // ---- layer 3 ----
        {
            const int ch8 = chq * 8;
            float4 bs0 = *(float4*)&b2s[ch8];
            float4 bs1 = *(float4*)&b2s[ch8 + 4];
            float pa[8] = {bs0.x, bs0.y, bs0.z, bs0.w, bs1.x, bs1.y, bs1.z, bs1.w};
            float pb[8] = {bs0.x, bs0.y, bs0.z, bs0.w, bs1.x, bs1.y, bs1.z, bs1.w};
            float qa[8] = {bs0.x, bs0.y, bs0.z, bs0.w, bs1.x, bs1.y, bs1.z, bs1.w};
            float qb[8] = {bs0.x, bs0.y, bs0.z, bs0.w, bs1.x, bs1.y, bs1.z, bs1.w};
            const float* p0 = hC0 + ns0 * D2;
            const float* p1 = hC0 + (ns0 + 1) * D2;
            const float* q0 = hC1 + ns0 * D2;
            const float* q1 = hC1 + (ns0 + 1) * D2;
#pragma unroll 2
            for (int d = 0; d < D2; d++) {
                float4 w0 = *(float4*)&W2s[d * D3 + ch8];
                float4 w1 = *(float4*)&W2s[d * D3 + ch8 + 4];
                float a = p0[d], b_ = p1[d], c = q0[d], e = q1[d];
                pa[0] = fmaf(a, w0.x, pa[0]); pa[1] = fmaf(a, w0.y, pa[1]);
                pa[2] = fmaf(a, w0.z, pa[2]); pa[3] = fmaf(a, w0.w, pa[3]);
                pa[4] = fmaf(a, w1.x, pa[4]); pa[5] = fmaf(a, w1.y, pa[5]);
                pa[6] = fmaf(a, w1.z, pa[6]); pa[7] = fmaf(a, w1.w, pa[7]);
                pb[0] = fmaf(b_, w0.x, pb[0]); pb[1] = fmaf(b_, w0.y, pb[1]);
                pb[2] = fmaf(b_, w0.z, pb[2]); pb[3] = fmaf(b_, w0.w, pb[3]);
                pb[4] = fmaf(b_, w1.x, pb[4]); pb[5] = fmaf(b_, w1.y, pb[5]);
                pb[6] = fmaf(b_, w1.z, pb[6]); pb[7] = fmaf(b_, w1.w, pb[7]);
                qa[0] = fmaf(c, w0.x, qa[0]); qa[1] = fmaf(c, w0.y, qa[1]);
                qa[2] = fmaf(c, w0.z, qa[2]); qa[3] = fmaf(c, w0.w, qa[3]);
                qa[4] = fmaf(c, w1.x, qa[4]); qa[5] = fmaf(c, w1.y, qa[5]);
                qa[6] = fmaf(c, w1.z, qa[6]); qa[7] = fmaf(c, w1.w, qa[7]);
                qb[0] = fmaf(e, w0.x, qb[0]); qb[1] = fmaf(e, w0.y, qb[1]);
                qb[2] = fmaf(e, w0.z, qb[2]); qb[3] = fmaf(e, w0.w, qb[3]);
                qb[4] = fmaf(e, w1.x, qb[4]); qb[5] = fmaf(e, w1.y, qb[5]);
                qb[6] = fmaf(e, w1.z, qb[6]); qb[7] = fmaf(e, w1.w, qb[7]);
            }
            *(float4*)&hB0[ns0 * D3 + ch8] =
                make_float4(fmaxf(pa[0], 0.f), fmaxf(pa[1], 0.f), fmaxf(pa[2], 0.f), fmaxf(pa[3], 0.f));
            *(float4*)&hB0[ns0 * D3 + ch8 + 4] =
                make_float4(fmaxf(pa[4], 0.f), fmaxf(pa[5], 0.f), fmaxf(pa[6], 0.f), fmaxf(pa[7], 0.f));
            *(float4*)&hB0[(ns0 + 1) * D3 + ch8] =
                make_float4(fmaxf(pb[0], 0.f), fmaxf(pb[1], 0.f), fmaxf(pb[2], 0.f), fmaxf(pb[3], 0.f));
            *(float4*)&hB0[(ns0 + 1) * D3 + ch8 + 4] =
                make_float4(fmaxf(pb[4], 0.f), fmaxf(pb[5], 0.f), fmaxf(pb[6], 0.f), fmaxf(pb[7], 0.f));
            *(float4*)&hB1[ns0 * D3 + ch8] =
                make_float4(fmaxf(qa[0], 0.f), fmaxf(qa[1], 0.f), fmaxf(qa[2], 0.f), fmaxf(qa[3], 0.f));
            *(float4*)&hB1[ns0 * D3 + ch8 + 4] =
                make_float4(fmaxf(qa[4], 0.f), fmaxf(qa[5], 0.f), fmaxf(qa[6], 0.f), fmaxf(qa[7], 0.f));
            *(float4*)&hB1[(ns0 + 1) * D3 + ch8] =
                make_float4(fmaxf(qb[0], 0.f), fmaxf(qb[1], 0.f), fmaxf(qb[2], 0.f), fmaxf(qb[3], 0.f));
            *(float4*)&hB1[(ns0 + 1) * D3 + ch8 + 4] =
                make_float4(fmaxf(qb[4], 0.f), fmaxf(qb[5], 0.f), fmaxf(qb[6], 0.f), fmaxf(qb[7], 0.f));
        }
        __syncthreads();

        {
            float* src = (tid < 128) ? hB0 : hB1;
            int dj = tid & 127;
            int cid = (tid < 128) ? cid0 : cid1;
            float m = src[dj];
#pragma unroll 4
            for (int ns = 1; ns < NNEI; ns++) m = fmaxf(m, src[ns * D3 + dj]);
            out_feat[(size_t)cid * D3 + dj] = m;
        }
        __syncthreads();
    }
}

// ---------------------------------------------------------------------------
extern "C" void kernel_launch(void* const* d_in, const int* in_sizes, int n_in,
                              void* d_out, int out_size) {
    const float* xyz  = (const float*)d_in[0];
    const float* feat = (const float*)d_in[1];
    const float* W0   = (const float*)d_in[2];
    const float* b0   = (const float*)d_in[3];
    const float* W1   = (const float*)d_in[4];
    const float* b1   = (const float*)d_in[5];
    const float* W2   = (const float*)d_in[6];
    const float* b2   = (const float*)d_in[7];

    float* out      = (float*)d_out;
    float* new_xyz  = out;                       // B*S*3
    float* out_feat = out + NB * NSMP * 3;       // B*S*128

    const int fps_smem = PPC * 3 * sizeof(float);               // 49152 B
    const int mlp_smem = (D0*D1 + D1*D2 + D2*D3 + D1 + D2 + D3
                          + 2*NNEI*D0 + 2*NNEI*D3 + 2*NNEI*D2) * 4;  // 133632 B
    cudaFuncSetAttribute(fps_cluster_kernel,
                         cudaFuncAttributeMaxDynamicSharedMemorySize, fps_smem);
    cudaFuncSetAttribute(group_mlp_kernel,
                         cudaFuncAttributeMaxDynamicSharedMemorySize, mlp_smem);

    fps_cluster_kernel<<<NB * FCTAS, FTHR, fps_smem>>>(xyz, new_xyz);

    const int bq_threads = 256;
    const int bq_blocks  = (NB * NSMP * 32 + bq_threads - 1) / bq_threads;
    ball_kernel<<<bq_blocks, bq_threads>>>(xyz, new_xyz);

    group_mlp_kernel<<<MLPC, 256, mlp_smem>>>(
        xyz, feat, W0, b0, W1, b1, W2, b2, new_xyz, out_feat);
}

// round 17
// speedup vs baseline: 1.0949x; 1.0949x over previous
#include <cuda_runtime.h>
#include <cooperative_groups.h>
#include <cstdint>

namespace cg = cooperative_groups;

#define NB    4
#define NPTS  16384
#define NC    64
#define NSMP  1024      // S (npoint)
#define NNEI  32        // nsample
#define D0    67        // 3 + C
#define D1    64
#define D2    64
#define D3    128

#define FCTAS 4                 // cluster size (CTAs per batch)
#define FTHR  512               // threads per FPS CTA
#define PPC   (NPTS / FCTAS)    // 4096 points per CTA
#define PPT   (PPC / FTHR)      // 8 points per thread
#define NWARP (FTHR / 32)       // 16 warps

#define NTASK (NB * NSMP)       // 4096 centroid tasks
#define NQUAD (NTASK / 4)       // 1024 task quads
#define MLPC  148               // persistent quad-task MLP CTAs (1 per SM)

// scratch: ball query neighbor indices
__device__ int g_ball_idx[NB * NSMP * NNEI];

__device__ __forceinline__ unsigned smem_u32(const void* p) {
    return (unsigned)__cvta_generic_to_shared(p);
}
__device__ __forceinline__ unsigned mapa_u32(unsigned laddr, unsigned rank) {
    unsigned r;
    asm("mapa.shared::cluster.u32 %0, %1, %2;" : "=r"(r) : "r"(laddr), "r"(rank));
    return r;
}
__device__ __forceinline__ void st_cluster_f4(unsigned raddr, float x, float y, float z, float w) {
    asm volatile("st.shared::cluster.v4.f32 [%0], {%1,%2,%3,%4};"
                 :: "r"(raddr), "f"(x), "f"(y), "f"(z), "f"(w) : "memory");
}
__device__ __forceinline__ void st_cluster_u32(unsigned raddr, unsigned v) {
    asm volatile("st.shared::cluster.u32 [%0], %1;" :: "r"(raddr), "r"(v) : "memory");
}
__device__ __forceinline__ unsigned redux_max_u32(unsigned v) {
    unsigned r;
    asm("redux.sync.max.u32 %0, %1, 0xffffffff;" : "=r"(r) : "r"(v));
    return r;
}
__device__ __forceinline__ unsigned redux_min_u32(unsigned v) {
    unsigned r;
    asm("redux.sync.min.u32 %0, %1, 0xffffffff;" : "=r"(r) : "r"(v));
    return r;
}
__device__ __forceinline__ void cluster_arrive() {
    asm volatile("barrier.cluster.arrive.aligned;" ::: "memory");
}
__device__ __forceinline__ void cluster_wait() {
    asm volatile("barrier.cluster.wait.aligned;" ::: "memory");
}

// ---------------------------------------------------------------------------
// FPS (R13, best measured 819us): one 4-CTA cluster per batch, 512 thr/CTA,
// 8 register-resident pts/thr. Global packed keys -> partition-invariant.
// ---------------------------------------------------------------------------
__global__ __launch_bounds__(FTHR, 1) __cluster_dims__(FCTAS, 1, 1)
void fps_cluster_kernel(const float* __restrict__ xyz, float* __restrict__ out_xyz) {
    extern __shared__ float dsm[];
    float* sx = dsm;
    float* sy = dsm + PPC;
    float* sz = dsm + 2 * PPC;
    __shared__ float4 s_rec[2][FCTAS];
    __shared__ unsigned s_lk[2][FCTAS];
    __shared__ unsigned long long s_wkey[NWARP];

    cg::cluster_group cluster = cg::this_cluster();
    const int crank = cluster.block_rank();
    const int b     = blockIdx.x / FCTAS;
    const int tid   = threadIdx.x;
    const int lane  = tid & 31;
    const int wid   = tid >> 5;

    const float* base = xyz + (size_t)b * NPTS * 3;
    const int g0 = crank * PPC;

    for (int k = tid; k < PPC * 3; k += FTHR) {
        float v = base[(size_t)g0 * 3 + k];
        int p = k / 3, c = k - 3 * p;
        if (c == 0)      sx[p] = v;
        else if (c == 1) sy[p] = v;
        else             sz[p] = v;
    }
    cluster.sync();

    float px[PPT], py[PPT], pz[PPT], dist[PPT];
#pragma unroll
    for (int j = 0; j < PPT; j++) {
        int i = tid + j * FTHR;
        px[j] = sx[i]; py[j] = sy[i]; pz[j] = sz[i];
        dist[j] = 3.4e38f;
    }

    unsigned a_rec[2], a_lk[2];
    if (wid == 0 && lane < FCTAS) {
        a_rec[0] = mapa_u32(smem_u32(&s_rec[0][crank]), lane);
        a_rec[1] = mapa_u32(smem_u32(&s_rec[1][crank]), lane);
        a_lk[0]  = mapa_u32(smem_u32(&s_lk[0][crank]),  lane);
        a_lk[1]  = mapa_u32(smem_u32(&s_lk[1][crank]),  lane);
    }

    float cx = base[0], cy = base[1], cz = base[2];
    float* oxy = out_xyz + (size_t)b * NSMP * 3;

    for (int s = 0; s < NSMP; s++) {
        if (crank == 0 && tid == 0) {
            oxy[s * 3 + 0] = cx; oxy[s * 3 + 1] = cy; oxy[s * 3 + 2] = cz;
        }

        float bv = -1.0f; int bi = 0;
#pragma unroll
        for (int j = 0; j < PPT; j++) {
            float dx = px[j] - cx, dy = py[j] - cy, dz = pz[j] - cz;
            float d  = dx * dx + dy * dy + dz * dz;
            float nd = fminf(dist[j], d);
            dist[j] = nd;
            if (nd > bv) { bv = nd; bi = tid + j * FTHR; }
        }

        unsigned db = __float_as_uint(bv);
        unsigned mx = redux_max_u32(db);
        unsigned gi = (unsigned)(g0 + bi);
        unsigned cand = (db == mx) ? gi : 0xffffffffu;
        unsigned mi = redux_min_u32(cand);
        if (lane == 0)
            s_wkey[wid] = ((unsigned long long)mx << 32) | (0xffffffffu - mi);
        __syncthreads();

        const int par = s & 1;
        if (wid == 0) {
            unsigned long long wk = (lane < NWARP) ? s_wkey[lane] : 0ull;
            unsigned hi2 = (unsigned)(wk >> 32);
            unsigned mx2 = redux_max_u32(hi2);
            unsigned cand2 = (hi2 == mx2) ? (unsigned)wk : 0u;
            unsigned lo2 = redux_max_u32(cand2);
            if (lane < FCTAS) {
                unsigned g  = 0xffffffffu - lo2;
                int li = (int)g - g0;
                st_cluster_f4(a_rec[par], sx[li], sy[li], sz[li],
                              __uint_as_float(mx2));
                st_cluster_u32(a_lk[par], lo2);
            }
        }
        cluster_arrive();
        cluster_wait();

        {
            unsigned long long km = 0ull;
            float X = 0.f, Y = 0.f, Z = 0.f;
#pragma unroll
            for (int r = 0; r < FCTAS; r++) {
                float4 rec = s_rec[par][r];
                unsigned lk = s_lk[par][r];
                unsigned long long ck =
                    ((unsigned long long)__float_as_uint(rec.w) << 32) | lk;
                if (ck > km) { km = ck; X = rec.x; Y = rec.y; Z = rec.z; }
            }
            cx = X; cy = Y; cz = Z;
        }
    }
}

// ---------------------------------------------------------------------------
// Ball query: one warp per centroid, 128-point pipelined chunks.
// ---------------------------------------------------------------------------
__global__ void ball_kernel(const float* __restrict__ xyz,
                            const float* __restrict__ new_xyz) {
    const int gw   = (blockIdx.x * blockDim.x + threadIdx.x) >> 5;
    const int lane = threadIdx.x & 31;
    if (gw >= NB * NSMP) return;
    const int b = gw >> 10;
    const float* base = xyz + (size_t)b * NPTS * 3;
    const float cx = new_xyz[gw * 3 + 0];
    const float cy = new_xyz[gw * 3 + 1];
    const float cz = new_xyz[gw * 3 + 2];
    const float r2 = 0.2f * 0.2f;
    int* out = g_ball_idx + gw * NNEI;

    int cnt = 0, first = 0;
    for (int j0 = 0; j0 < NPTS && cnt < NNEI; j0 += 128) {
        float d2v[4];
#pragma unroll
        for (int c = 0; c < 4; c++) {
            const int j = j0 + c * 32 + lane;
            float dx = base[3 * j]     - cx;
            float dy = base[3 * j + 1] - cy;
            float dz = base[3 * j + 2] - cz;
            d2v[c] = dx * dx + dy * dy + dz * dz;
        }
#pragma unroll
        for (int c = 0; c < 4; c++) {
            bool hit = (d2v[c] <= r2);
            unsigned m = __ballot_sync(0xffffffffu, hit);
            if (m) {
                if (cnt == 0) first = j0 + c * 32 + (__ffs(m) - 1);
                int pos = cnt + __popc(m & ((1u << lane) - 1u));
                if (hit && pos < NNEI) out[pos] = j0 + c * 32 + lane;
                cnt += __popc(m);
            }
        }
    }
    if (cnt < NNEI) {
        for (int p = cnt + lane; p < NNEI; p += 32) out[p] = first;
    }
}

// ---------------------------------------------------------------------------
// Quad-task persistent MLP: 148 CTAs (1/SM, occupancy 1, ~167KB smem).
// Each iteration processes FOUR centroids; every weight float4 load feeds
// all four tasks' accumulators. hC aliases the dead hA region per task.
// Per-output accumulation order identical to proven kernels -> bit-identical.
// ---------------------------------------------------------------------------
__global__ __launch_bounds__(256, 1)
void group_mlp_kernel(const float* __restrict__ xyz,
                      const float* __restrict__ feat,
                      const float* __restrict__ W0, const float* __restrict__ b0,
                      const float* __restrict__ W1, const float* __restrict__ b1,
                      const float* __restrict__ W2, const float* __restrict__ b2,
                      const float* __restrict__ new_xyz,
                      float* __restrict__ out_feat) {
    extern __shared__ float sm[];
    float* W0s = sm;                    // 4288
    float* W1s = W0s + D0 * D1;         // 4096
    float* W2s = W1s + D1 * D2;         // 8192
    float* b0s = W2s + D2 * D3;         // 64
    float* b1s = b0s + D1;              // 64
    float* b2s = b1s + D2;              // 128
    float* hbase = b2s + D3;
    // per task t: hAC (2144, holds hA then aliased as hC) and hB (4096)
    float* hAC[4];
    float* hB[4];
#pragma unroll
    for (int t = 0; t < 4; t++) {
        hAC[t] = hbase + t * (NNEI * D0 + NNEI * D3);
        hB[t]  = hAC[t] + NNEI * D0;
    }

    const int tid = threadIdx.x;
    const int chq = tid & 15;
    const int ns0 = (tid >> 4) * 2;

    for (int i = tid; i < D0 * D1; i += 256) W0s[i] = W0[i];
    for (int i = tid; i < D1 * D2; i += 256) W1s[i] = W1[i];
    for (int i = tid; i < D2 * D3; i += 256) W2s[i] = W2[i];
    if (tid < D1) b0s[tid] = b0[tid];
    if (tid < D2) b1s[tid] = b1[tid];
    if (tid < D3) b2s[tid] = b2[tid];
    __syncthreads();

    for (int q = blockIdx.x; q < NQUAD; q += MLPC) {
        const int cid0 = 4 * q;               // 4 consecutive cids, same batch
        const int ba = cid0 >> 10;
        const float* xb = xyz  + (size_t)ba * NPTS * 3;
        const float* fb = feat + (size_t)ba * NPTS * NC;

        // build h0 for all four tasks
#pragma unroll
        for (int t = 0; t < 4; t++) {
            const int* ni = g_ball_idx + (cid0 + t) * NNEI;
            for (int e = tid; e < NNEI * 3; e += 256) {
                int ns = e / 3, k = e - 3 * ns;
                hAC[t][ns * D0 + k] = xb[(size_t)__ldg(ni + ns) * 3 + k]
                                      - new_xyz[(cid0 + t) * 3 + k];
            }
            for (int e = tid; e < NNEI * NC; e += 256) {
                int ns = e >> 6, c = e & 63;
                hAC[t][ns * D0 + 3 + c] = fb[(size_t)__ldg(ni + ns) * NC + c];
            }
        }
        __syncthreads();

        // ---- layer 1: hA(67) -> hB(64), 4 tasks x 2 ns x 4 ch per thread ----
        {
            float4 bs = *(float4*)&b0s[chq * 4];
            float a[4][8];
#pragma unroll
            for (int t = 0; t < 4; t++) {
                a[t][0] = bs.x; a[t][1] = bs.y; a[t][2] = bs.z; a[t][3] = bs.w;
                a[t][4] = bs.x; a[t][5] = bs.y; a[t][6] = bs.z; a[t][7] = bs.w;
            }
#pragma unroll 4
            for (int d = 0; d < D0; d++) {
                float4 w = *(float4*)&W0s[d * D1 + chq * 4];
#pragma unroll
                for (int t = 0; t < 4; t++) {
                    float v0 = hAC[t][ns0 * D0 + d];
                    float v1 = hAC[t][(ns0 + 1) * D0 + d];
                    a[t][0] = fmaf(v0, w.x, a[t][0]);
                    a[t][1] = fmaf(v0, w.y, a[t][1]);
                    a[t][2] = fmaf(v0, w.z, a[t][2]);
                    a[t][3] = fmaf(v0, w.w, a[t][3]);
                    a[t][4] = fmaf(v1, w.x, a[t][4]);
                    a[t][5] = fmaf(v1, w.y, a[t][5]);
                    a[t][6] = fmaf(v1, w.z, a[t][6]);
                    a[t][7] = fmaf(v1, w.w, a[t][7]);
                }
            }
#pragma unroll
            for (int t = 0; t < 4; t++) {
                *(float4*)&hB[t][ns0 * D1 + chq * 4] =
                    make_float4(fmaxf(a[t][0], 0.f), fmaxf(a[t][1], 0.f),
                                fmaxf(a[t][2], 0.f), fmaxf(a[t][3], 0.f));
                *(float4*)&hB[t][(ns0 + 1) * D1 + chq * 4] =
                    make_float4(fmaxf(a[t][4], 0.f), fmaxf(a[t][5], 0.f),
                                fmaxf(a[t][6], 0.f), fmaxf(a[t][7], 0.f));
            }
        }
        __syncthreads();

        // ---- layer 2: hB(64) -> hC(64) [hC aliases hA region] ----
        {
            float4 bs = *(float4*)&b1s[chq * 4];
            float a[4][8];
#pragma unroll
            for (int t = 0; t < 4; t++) {
                a[t][0] = bs.x; a[t][1] = bs.y; a[t][2] = bs.z; a[t][3] = bs.w;
                a[t][4] = bs.x; a[t][5] = bs.y; a[t][6] = bs.z; a[t][7] = bs.w;
            }
#pragma unroll 4
            for (int d = 0; d < D1; d++) {
                float4 w = *(float4*)&W1s[d * D2 + chq * 4];
#pragma unroll
                for (int t = 0; t < 4; t++) {
                    float v0 = hB[t][ns0 * D1 + d];
                    float v1 = hB[t][(ns0 + 1) * D1 + d];
                    a[t][0] = fmaf(v0, w.x, a[t][0]);
                    a[t][1] = fmaf(v0, w.y, a[t][1]);
                    a[t][2] = fmaf(v0, w.z, a[t][2]);
                    a[t][3] = fmaf(v0, w.w, a[t][3]);
                    a[t][4] = fmaf(v1, w.x, a[t][4]);
                    a[t][5] = fmaf(v1, w.y, a[t][5]);
                    a[t][6] = fmaf(v1, w.z, a[t][6]);
                    a[t][7] = fmaf(v1, w.w, a[t][7]);
                }
            }
#pragma unroll
            for (int t = 0; t < 4; t++) {
                *(float4*)&hAC[t][ns0 * D2 + chq * 4] =
                    make_float4(fmaxf(a[t][0], 0.f), fmaxf(a[t][1], 0.f),
                                fmaxf(a[t][2], 0.f), fmaxf(a[t][3], 0.f));
                *(float4*)&hAC[t][(ns0 + 1) * D2 + chq * 4] =
                    make_float4(fmaxf(a[t][4], 0.f), fmaxf(a[t][5], 0.f),
                                fmaxf(a[t][6], 0.f), fmaxf(a[t][7], 0.f));
            }
        }
        __syncthreads();

        // ---- layer 3: hC(64) -> hB(128), 4 tasks x 2 ns x 8 ch per thread ----
        {
            const int ch8 = chq * 8;
            float4 bs0 = *(float4*)&b2s[ch8];
            float4 bs1 = *(float4*)&b2s[ch8 + 4];
            float a[4][16];
#pragma unroll
            for (int t = 0; t < 4; t++) {
                a[t][0] = bs0.x; a[t][1] = bs0.y; a[t][2] = bs0.z; a[t][3] = bs0.w;
                a[t][4] = bs1.x; a[t][5] = bs1.y; a[t][6] = bs1.z; a[t][7] = bs1.w;
                a[t][8] = bs0.x; a[t][9] = bs0.y; a[t][10] = bs0.z; a[t][11] = bs0.w;
                a[t][12] = bs1.x; a[t][13] = bs1.y; a[t][14] = bs1.z; a[t][15] = bs1.w;
            }
#pragma unroll 2
            for (int d = 0; d < D2; d++) {
                float4 w0 = *(float4*)&W2s[d * D3 + ch8];
                float4 w1 = *(float4*)&W2s[d * D3 + ch8 + 4];
#pragma unroll
                for (int t = 0; t < 4; t++) {
                    float v0 = hAC[t][ns0 * D2 + d];
                    float v1 = hAC[t][(ns0 + 1) * D2 + d];
                    a[t][0]  = fmaf(v0, w0.x, a[t][0]);
                    a[t][1]  = fmaf(v0, w0.y, a[t][1]);
                    a[t][2]  = fmaf(v0, w0.z, a[t][2]);
                    a[t][3]  = fmaf(v0, w0.w, a[t][3]);
                    a[t][4]  = fmaf(v0, w1.x, a[t][4]);
                    a[t][5]  = fmaf(v0, w1.y, a[t][5]);
                    a[t][6]  = fmaf(v0, w1.z, a[t][6]);
                    a[t][7]  = fmaf(v0, w1.w, a[t][7]);
                    a[t][8]  = fmaf(v1, w0.x, a[t][8]);
                    a[t][9]  = fmaf(v1, w0.y, a[t][9]);
                    a[t][10] = fmaf(v1, w0.z, a[t][10]);
                    a[t][11] = fmaf(v1, w0.w, a[t][11]);
                    a[t][12] = fmaf(v1, w1.x, a[t][12]);
                    a[t][13] = fmaf(v1, w1.y, a[t][13]);
                    a[t][14] = fmaf(v1, w1.z, a[t][14]);
                    a[t][15] = fmaf(v1, w1.w, a[t][15]);
                }
            }
#pragma unroll
            for (int t = 0; t < 4; t++) {
                *(float4*)&hB[t][ns0 * D3 + ch8] =
                    make_float4(fmaxf(a[t][0], 0.f), fmaxf(a[t][1], 0.f),
                                fmaxf(a[t][2], 0.f), fmaxf(a[t][3], 0.f));
                *(float4*)&hB[t][ns0 * D3 + ch8 + 4] =
                    make_float4(fmaxf(a[t][4], 0.f), fmaxf(a[t][5], 0.f),
                                fmaxf(a[t][6], 0.f), fmaxf(a[t][7], 0.f));
                *(float4*)&hB[t][(ns0 + 1) * D3 + ch8] =
                    make_float4(fmaxf(a[t][8], 0.f), fmaxf(a[t][9], 0.f),
                                fmaxf(a[t][10], 0.f), fmaxf(a[t][11], 0.f));
                *(float4*)&hB[t][(ns0 + 1) * D3 + ch8 + 4] =
                    make_float4(fmaxf(a[t][12], 0.f), fmaxf(a[t][13], 0.f),
                                fmaxf(a[t][14], 0.f), fmaxf(a[t][15], 0.f));
            }
        }
        __syncthreads();

        // ---- maxpool over neighbors: 4 tasks x 128 ch = 512 outputs ----
        for (int o = tid; o < 4 * D3; o += 256) {
            int t = o >> 7, dj = o & 127;
            float m = hB[t][dj];
#pragma unroll 4
            for (int ns = 1; ns < NNEI; ns++) m = fmaxf(m, hB[t][ns * D3 + dj]);
            out_feat[(size_t)(cid0 + t) * D3 + dj] = m;
        }
        __syncthreads();
    }
}

// ---------------------------------------------------------------------------
extern "C" void kernel_launch(void* const* d_in, const int* in_sizes, int n_in,
                              void* d_out, int out_size) {
    const float* xyz  = (const float*)d_in[0];
    const float* feat = (const float*)d_in[1];
    const float* W0   = (const float*)d_in[2];
    const float* b0   = (const float*)d_in[3];
    const float* W1   = (const float*)d_in[4];
    const float* b1   = (const float*)d_in[5];
    const float* W2   = (const float*)d_in[6];
    const float* b2   = (const float*)d_in[7];

    float* out      = (float*)d_out;
    float* new_xyz  = out;                       // B*S*3
    float* out_feat = out + NB * NSMP * 3;       // B*S*128

    const int fps_smem = PPC * 3 * sizeof(float);               // 49152 B
    const int mlp_smem = (D0*D1 + D1*D2 + D2*D3 + D1 + D2 + D3
                          + 4 * (NNEI*D0 + NNEI*D3)) * 4;       // 167168 B
    cudaFuncSetAttribute(fps_cluster_kernel,
                         cudaFuncAttributeMaxDynamicSharedMemorySize, fps_smem);
    cudaFuncSetAttribute(group_mlp_kernel,
                         cudaFuncAttributeMaxDynamicSharedMemorySize, mlp_smem);

    fps_cluster_kernel<<<NB * FCTAS, FTHR, fps_smem>>>(xyz, new_xyz);

    const int bq_threads = 256;
    const int bq_blocks  = (NB * NSMP * 32 + bq_threads - 1) / bq_threads;
    ball_kernel<<<bq_blocks, bq_threads>>>(xyz, new_xyz);

    group_mlp_kernel<<<MLPC, 256, mlp_smem>>>(
        xyz, feat, W0, b0, W1, b1, W2, b2, new_xyz, out_feat);
}